// round 1
// baseline (speedup 1.0000x reference)
#include <cuda_runtime.h>
#include <cstddef>

// BilinearMixture: out[e,c] = sum_w (sum_d u[ui,d]*W[w,d]*v[vi,d]) * scalars[w,c]
//                           + u_bias[ui,c] + v_bias[vi,c]
// E=2e6, D=128, NUM_W=3, C=5.
// One warp per edge: lane l holds float4 covering d = 4l..4l+3.

#define D 128
#define NUM_W 3
#define NUM_C 5
#define WARPS_PER_BLOCK 8
#define THREADS (WARPS_PER_BLOCK * 32)

__global__ __launch_bounds__(THREADS)
void bilinear_mixture_kernel(
    const float* __restrict__ u_feats,
    const float* __restrict__ v_feats,
    const int*   __restrict__ u_idx,
    const int*   __restrict__ v_idx,
    const float* __restrict__ W,
    const float* __restrict__ scalars,
    const float* __restrict__ u_bias,
    const float* __restrict__ v_bias,
    float*       __restrict__ out,
    int E)
{
    __shared__ float sW[NUM_W * D];
    __shared__ float sS[NUM_W * NUM_C];

    int tid = threadIdx.x;
    for (int i = tid; i < NUM_W * D; i += THREADS) sW[i] = W[i];
    if (tid < NUM_W * NUM_C) sS[tid] = scalars[tid];
    __syncthreads();

    int lane = tid & 31;
    int warp = tid >> 5;
    int e = blockIdx.x * WARPS_PER_BLOCK + warp;
    if (e >= E) return;

    int ui = u_idx[e];
    int vi = v_idx[e];

    const float4* urow = reinterpret_cast<const float4*>(u_feats + (size_t)ui * D);
    const float4* vrow = reinterpret_cast<const float4*>(v_feats + (size_t)vi * D);
    float4 u4 = __ldg(urow + lane);
    float4 v4 = __ldg(vrow + lane);

    float p0 = u4.x * v4.x;
    float p1 = u4.y * v4.y;
    float p2 = u4.z * v4.z;
    float p3 = u4.w * v4.w;

    float b[NUM_W];
#pragma unroll
    for (int w = 0; w < NUM_W; w++) {
        const float4 w4 = reinterpret_cast<const float4*>(sW + w * D)[lane];
        b[w] = fmaf(p0, w4.x, fmaf(p1, w4.y, fmaf(p2, w4.z, p3 * w4.w)));
    }

    // Butterfly reduction: all lanes end with the full sums.
#pragma unroll
    for (int off = 16; off; off >>= 1) {
#pragma unroll
        for (int w = 0; w < NUM_W; w++)
            b[w] += __shfl_xor_sync(0xffffffffu, b[w], off);
    }

    if (lane < NUM_C) {
        float o = fmaf(b[0], sS[0 * NUM_C + lane],
                  fmaf(b[1], sS[1 * NUM_C + lane],
                       b[2] * sS[2 * NUM_C + lane]));
        o += u_bias[(size_t)ui * NUM_C + lane];
        o += v_bias[(size_t)vi * NUM_C + lane];
        out[(size_t)e * NUM_C + lane] = o;
    }
}

extern "C" void kernel_launch(void* const* d_in, const int* in_sizes, int n_in,
                              void* d_out, int out_size)
{
    const float* u_feats = (const float*)d_in[0];
    const float* v_feats = (const float*)d_in[1];
    const int*   u_idx   = (const int*)  d_in[2];
    const int*   v_idx   = (const int*)  d_in[3];
    const float* W       = (const float*)d_in[4];
    const float* scalars = (const float*)d_in[5];
    const float* u_bias  = (const float*)d_in[6];
    const float* v_bias  = (const float*)d_in[7];
    float* out = (float*)d_out;

    int E = in_sizes[2];  // u_idx element count
    int blocks = (E + WARPS_PER_BLOCK - 1) / WARPS_PER_BLOCK;
    bilinear_mixture_kernel<<<blocks, THREADS>>>(
        u_feats, v_feats, u_idx, v_idx, W, scalars, u_bias, v_bias, out, E);
}

// round 2
// speedup vs baseline: 1.1588x; 1.1588x over previous
#include <cuda_runtime.h>
#include <cstddef>

// BilinearMixture: out[e,c] = sum_w (sum_d u[ui,d]*W[w,d]*v[vi,d]) * scalars[w,c]
//                           + u_bias[ui,c] + v_bias[vi,c]
// E=2e6, D=128, NUM_W=3, C=5.
//
// Layout: 8 lanes per edge, 4 edges per warp. Lane l (0..7) of group g owns
// d in { i*32 + l*4 .. +3 : i=0..3 }  (interleaved so each LDG.128 instruction
// covers one contiguous 128B line per group -> 4 wf/instruction warp-wide).
// W held in registers (48/lane), loaded once per thread (persistent loop).
// No shared memory, no LDS in the hot loop.

#define D 128
#define NUM_W 3
#define NUM_C 5
#define THREADS 256
#define WARPS_PER_BLOCK (THREADS / 32)
#define EDGES_PER_WARP 4
#define GRID_BLOCKS 1184   // 148 SMs * 8; grid-stride loop covers all edges

__global__ __launch_bounds__(THREADS)
void bilinear_mixture_kernel(
    const float* __restrict__ u_feats,
    const float* __restrict__ v_feats,
    const int*   __restrict__ u_idx,
    const int*   __restrict__ v_idx,
    const float* __restrict__ W,
    const float* __restrict__ scalars,
    const float* __restrict__ u_bias,
    const float* __restrict__ v_bias,
    float*       __restrict__ out,
    int E)
{
    const int tid  = threadIdx.x;
    const int lane = tid & 31;
    const int l    = lane & 7;        // lane within edge-group
    const int g    = lane >> 3;       // edge-group within warp (0..3)

    // --- Per-lane constants, loaded once ---
    // W slice for this lane: Wreg[w][i] = float4 at W row w, float4 index i*8+l
    float4 Wreg[NUM_W][4];
    {
        const float4* Wp = reinterpret_cast<const float4*>(W);
#pragma unroll
        for (int w = 0; w < NUM_W; w++)
#pragma unroll
            for (int i = 0; i < 4; i++)
                Wreg[w][i] = Wp[w * (D / 4) + i * 8 + l];
    }
    // scalars column for this lane's output class
    float s0 = 0.f, s1 = 0.f, s2 = 0.f;
    if (l < NUM_C) {
        s0 = scalars[0 * NUM_C + l];
        s1 = scalars[1 * NUM_C + l];
        s2 = scalars[2 * NUM_C + l];
    }

    const int warp        = tid >> 5;
    const int global_warp = blockIdx.x * WARPS_PER_BLOCK + warp;
    const int total_warps = gridDim.x * WARPS_PER_BLOCK;
    const long long stride = (long long)total_warps * EDGES_PER_WARP;

    for (long long e_base = (long long)global_warp * EDGES_PER_WARP;
         e_base < E; e_base += stride)
    {
        const long long e = e_base + g;
        const bool valid = (e < E);
        const int ui = valid ? u_idx[e] : 0;
        const int vi = valid ? v_idx[e] : 0;

        const float4* up = reinterpret_cast<const float4*>(u_feats) + (size_t)ui * (D / 4);
        const float4* vp = reinterpret_cast<const float4*>(v_feats) + (size_t)vi * (D / 4);

        float4 u4[4], v4[4];
#pragma unroll
        for (int i = 0; i < 4; i++) {
            u4[i] = up[i * 8 + l];
            v4[i] = vp[i * 8 + l];
        }

        float b0 = 0.f, b1 = 0.f, b2 = 0.f;
#pragma unroll
        for (int i = 0; i < 4; i++) {
            const float p0 = u4[i].x * v4[i].x;
            const float p1 = u4[i].y * v4[i].y;
            const float p2 = u4[i].z * v4[i].z;
            const float p3 = u4[i].w * v4[i].w;
            b0 = fmaf(p0, Wreg[0][i].x, fmaf(p1, Wreg[0][i].y,
                 fmaf(p2, Wreg[0][i].z, fmaf(p3, Wreg[0][i].w, b0))));
            b1 = fmaf(p0, Wreg[1][i].x, fmaf(p1, Wreg[1][i].y,
                 fmaf(p2, Wreg[1][i].z, fmaf(p3, Wreg[1][i].w, b1))));
            b2 = fmaf(p0, Wreg[2][i].x, fmaf(p1, Wreg[2][i].y,
                 fmaf(p2, Wreg[2][i].z, fmaf(p3, Wreg[2][i].w, b2))));
        }

        // Butterfly over the 8-lane group: 3 rounds x 3 values.
#pragma unroll
        for (int off = 4; off; off >>= 1) {
            b0 += __shfl_xor_sync(0xffffffffu, b0, off);
            b1 += __shfl_xor_sync(0xffffffffu, b1, off);
            b2 += __shfl_xor_sync(0xffffffffu, b2, off);
        }

        if (valid && l < NUM_C) {
            float o = fmaf(b0, s0, fmaf(b1, s1, b2 * s2));
            o += u_bias[(size_t)ui * NUM_C + l];
            o += v_bias[(size_t)vi * NUM_C + l];
            out[(size_t)e * NUM_C + l] = o;
        }
    }
}

extern "C" void kernel_launch(void* const* d_in, const int* in_sizes, int n_in,
                              void* d_out, int out_size)
{
    const float* u_feats = (const float*)d_in[0];
    const float* v_feats = (const float*)d_in[1];
    const int*   u_idx   = (const int*)  d_in[2];
    const int*   v_idx   = (const int*)  d_in[3];
    const float* W       = (const float*)d_in[4];
    const float* scalars = (const float*)d_in[5];
    const float* u_bias  = (const float*)d_in[6];
    const float* v_bias  = (const float*)d_in[7];
    float* out = (float*)d_out;

    int E = in_sizes[2];  // u_idx element count

    // Persistent-ish grid; grid-stride loop covers all edges.
    long long needed_warps = ((long long)E + EDGES_PER_WARP - 1) / EDGES_PER_WARP;
    long long needed_blocks = (needed_warps + WARPS_PER_BLOCK - 1) / WARPS_PER_BLOCK;
    int blocks = (int)(needed_blocks < GRID_BLOCKS ? needed_blocks : GRID_BLOCKS);

    bilinear_mixture_kernel<<<blocks, THREADS>>>(
        u_feats, v_feats, u_idx, v_idx, W, scalars, u_bias, v_bias, out, E);
}